// round 11
// baseline (speedup 1.0000x reference)
#include <cuda_runtime.h>
#include <cuda_bf16.h>

// HGNN forward, ONE kernel, no inter-block communication.
// Grid (256 graphs x 4 f-quarters), 128 threads. Block (b,fq) owns 16 f's.
//   Y[v,f]  = sum_d x[v,d] * W[f,d]              (v in graph b, f in quarter)
//   ED[e,f] = relu((1/32) sum_v H[v,e]*Y[v,f] + bias[f])   -> h_e stripe
//   c[b,f]  = (1/(32*48)) sum_e s[e]*ED[e,f], s[e]=sum_v H[v,e]
// Each block owns ALL e for its f's -> writes c directly. No scratch/atomics.
// Output buffer: [ c (B*D) | h_e (B*E*D) ]

constexpr int V   = 8192;
constexpr int E   = 48;
constexpr int D   = 64;
constexpr int B   = 256;
constexpr int NPG = V / B;     // 32 nodes per graph
constexpr int NT  = 128;
constexpr int FQ  = 16;        // f's per block
constexpr int WSQ = 68;        // W-quarter shared row stride
constexpr int YS  = 17;        // Ys row stride (padded)

__global__ __launch_bounds__(NT, 8) void hgnn_fused_kernel(
    const float* __restrict__ x,     // (V, D)
    const float* __restrict__ Hm,    // (V, E)
    const float* __restrict__ W,     // (D, D) row-major [f][d]
    const float* __restrict__ bias,  // (D,)
    float* __restrict__ out)         // [c | h_e]
{
    __shared__ float Xs[NPG * D];    // 8 KB
    __shared__ float Wq[FQ * WSQ];   // 4.25 KB : Wq[u*68+d] = W[(fq*16+u)*64+d]
    __shared__ float Ht[E * NPG];    // 6 KB    : Ht[e*32+v]
    __shared__ float Ys[NPG * YS];   // 2.1 KB  : Ys[v*17+u]
    __shared__ float Sv[E];
    __shared__ float Bq[FQ];
    __shared__ float Cp[8][FQ];

    const int b  = blockIdx.x;
    const int fq = blockIdx.y;
    const int t  = threadIdx.x;
    const int u  = t & 15;           // f within quarter
    const int g  = t >> 4;           // 0..7 group

    // ---- staging (all coalesced LDG.128) ----
    {
        const float4* xg = (const float4*)(x + (size_t)b * NPG * D);
        #pragma unroll
        for (int i = t; i < NPG * D / 4; i += NT) ((float4*)Xs)[i] = xg[i];

        const float4* wg = (const float4*)(W + (size_t)fq * FQ * D);
        #pragma unroll
        for (int i = t; i < FQ * D / 4; i += NT) {
            float4 w = wg[i];
            int uu = i >> 4, d4 = (i & 15) * 4;
            *(float4*)&Wq[uu * WSQ + d4] = w;
        }

        const float4* hb = (const float4*)(Hm + (size_t)b * NPG * E);
        #pragma unroll
        for (int i = t; i < NPG * E / 4; i += NT) {      // 384; E%4==0
            float4 h = hb[i];
            int base = i * 4;
            int v = base / E;
            int e = base - v * E;
            Ht[(e + 0) * NPG + v] = h.x;
            Ht[(e + 1) * NPG + v] = h.y;
            Ht[(e + 2) * NPG + v] = h.z;
            Ht[(e + 3) * NPG + v] = h.w;
        }
        if (t < FQ) Bq[t] = bias[fq * FQ + t];
    }
    __syncthreads();

    // ---- s[e] = sum_v Ht[e,v] ----
    if (t < E) {
        const float4* hr = (const float4*)&Ht[t * NPG];
        float a0 = 0.f, a1 = 0.f;
        #pragma unroll
        for (int k = 0; k < NPG / 8; k++) {
            float4 h0 = hr[2 * k], h1 = hr[2 * k + 1];
            a0 += h0.x + h0.y + h0.z + h0.w;
            a1 += h1.x + h1.y + h1.z + h1.w;
        }
        Sv[t] = a0 + a1;
    }

    // ---- Y[v, u] = sum_d Xs[v,d] * Wq[u,d] ; v = g*4+j ----
    {
        float ya[4] = {0.f, 0.f, 0.f, 0.f};
        #pragma unroll
        for (int dc = 0; dc < 4; dc++) {
            float4 wv[4];
            const float4* wr = (const float4*)&Wq[u * WSQ + dc * 16];  // cf
            #pragma unroll
            for (int k = 0; k < 4; k++) wv[k] = wr[k];

            #pragma unroll
            for (int j = 0; j < 4; j++) {
                int v = g * 4 + j;
                const float4* xr = (const float4*)&Xs[v * D + dc * 16]; // bcast
                #pragma unroll
                for (int k = 0; k < 4; k++) {
                    float4 xx = xr[k];
                    ya[j] = fmaf(xx.x, wv[k].x, ya[j]);
                    ya[j] = fmaf(xx.y, wv[k].y, ya[j]);
                    ya[j] = fmaf(xx.z, wv[k].z, ya[j]);
                    ya[j] = fmaf(xx.w, wv[k].w, ya[j]);
                }
            }
        }
        #pragma unroll
        for (int j = 0; j < 4; j++) Ys[(g * 4 + j) * YS + u] = ya[j];
    }
    __syncthreads();

    // ---- ED[e,u] = sum_v Ht[e,v] * Ys[v,u] ; e = g + 8j ----
    float acc[6] = {0.f, 0.f, 0.f, 0.f, 0.f, 0.f};
    #pragma unroll
    for (int vc = 0; vc < 2; vc++) {
        float yr[16];
        #pragma unroll
        for (int v = 0; v < 16; v++)
            yr[v] = Ys[(vc * 16 + v) * YS + u];           // conflict-free

        #pragma unroll
        for (int j = 0; j < 6; j++) {
            int e = g + 8 * j;
            const float4* hr = (const float4*)&Ht[e * NPG + vc * 16];  // bcast
            #pragma unroll
            for (int k = 0; k < 4; k++) {
                float4 h = hr[k];
                acc[j] = fmaf(h.x, yr[4 * k + 0], acc[j]);
                acc[j] = fmaf(h.y, yr[4 * k + 1], acc[j]);
                acc[j] = fmaf(h.z, yr[4 * k + 2], acc[j]);
                acc[j] = fmaf(h.w, yr[4 * k + 3], acc[j]);
            }
        }
    }

    // ---- relu, h_e stripe, c fold ----
    {
        const float bf = Bq[u];
        float cacc = 0.f;
        float* he = out + (size_t)B * D + (size_t)b * E * D + fq * FQ;
        #pragma unroll
        for (int j = 0; j < 6; j++) {
            int e = g + 8 * j;
            float r = fmaxf(fmaf(acc[j], 1.0f / NPG, bf), 0.f);
            he[(size_t)e * D + u] = r;
            cacc = fmaf(Sv[e], r, cacc);
        }
        Cp[g][u] = cacc;
    }
    __syncthreads();

    if (t < FQ) {
        float s = 0.f;
        #pragma unroll
        for (int k = 0; k < 8; k++) s += Cp[k][t];
        out[b * D + fq * FQ + t] = s * (1.0f / (NPG * E));
    }
}

extern "C" void kernel_launch(void* const* d_in, const int* in_sizes, int n_in,
                              void* d_out, int out_size) {
    const float* x    = (const float*)d_in[0];   // (V,D)
    const float* Hm   = (const float*)d_in[1];   // (V,E)
    const float* W    = (const float*)d_in[2];   // (D,D)
    const float* bias = (const float*)d_in[3];   // (D,)
    float* out = (float*)d_out;

    dim3 grid(B, D / FQ);
    hgnn_fused_kernel<<<grid, NT>>>(x, Hm, W, bias, out);
}

// round 12
// speedup vs baseline: 1.1333x; 1.1333x over previous
#include <cuda_runtime.h>
#include <cuda_bf16.h>

// HGNN forward, single kernel. Grid (256 graphs x 4 e-quarters), 128 threads.
//   Per block: 12 hyperedges of one graph.
//   M[e,d]  = (1/32) * sum_v H[v,e]*x[v,d]
//   ED[e,f] = relu(sum_d M[e,d]*W[f,d] + b[f])  -> h_e
//   partial c -> Cscratch (stcg); last quarter-block per graph via
//   atom.add.acq_rel.gpu counter sums partials in fixed order, writes c.
// Output buffer: [ c (B*D) | h_e (B*E*D) ]
//
// R12 = R8 (best) + Blackwell packed fma.rn.f32x2: FFMA instruction count
// halved (576 -> 288/thread). Phase-1 packs over v-pairs, phase-2 over
// d-pairs; packed operands come directly from 16B shared loads.

constexpr int V   = 8192;
constexpr int E   = 48;
constexpr int D   = 64;
constexpr int B   = 256;
constexpr int NPG = V / B;        // 32 nodes per graph
constexpr int EQN = 4;            // e-quarters
constexpr int EPB = E / EQN;      // 12 edges per block
constexpr int NT  = 128;
constexpr int WS  = 68;           // W shared row stride (floats)

typedef unsigned long long ull;

__device__ __forceinline__ void ffma2(ull& acc, ull a, ull b) {
    asm("fma.rn.f32x2 %0, %1, %2, %0;" : "+l"(acc) : "l"(a), "l"(b));
}
__device__ __forceinline__ ull pack2(float lo, float hi) {
    ull r;
    asm("mov.b64 %0, {%1, %2};" : "=l"(r) : "f"(lo), "f"(hi));
    return r;
}
__device__ __forceinline__ float sum2(ull v) {
    float lo, hi;
    asm("mov.b64 {%0, %1}, %2;" : "=f"(lo), "=f"(hi) : "l"(v));
    return lo + hi;
}

__device__ float Cscratch[EQN * B * D];   // partial-c scratch (L2 via stcg)
__device__ int   Ctr[B];                  // arrival counters (zero-init; reset by last block)

__global__ __launch_bounds__(NT, 8) void hgnn_main_kernel(
    const float* __restrict__ x,     // (V, D)
    const float* __restrict__ Hm,    // (V, E)
    const float* __restrict__ W,     // (D, D) row-major [f][d]
    const float* __restrict__ bias,  // (D,)
    float* __restrict__ out)         // [c | h_e]
{
    __shared__ float Ht[EPB * NPG];   // transposed H slice (1.5 KB)
    __shared__ float Ws[D * WS];      // W rows, stride 68 (17 KB)
    __shared__ float Ms[EPB * D];     // (3 KB)
    __shared__ float Sv[EPB];
    __shared__ float Bs[D];
    __shared__ float Cp[4][D];
    __shared__ int   isLast;

    const int b  = blockIdx.x;
    const int eq = blockIdx.y;
    const int t  = threadIdx.x;

    // ---- stage H slice transposed: Ht[e*32+v] = H[v, eq*12+e] ----
    {
        const float* hb = Hm + (size_t)b * NPG * E + eq * EPB;
        if (t < NPG * 3) {                       // 96 float4 loads
            int v = t / 3, g = t - (t / 3) * 3;
            float4 h = *(const float4*)(hb + v * E + g * 4);
            int e = g * 4;
            Ht[(e + 0) * NPG + v] = h.x;
            Ht[(e + 1) * NPG + v] = h.y;
            Ht[(e + 2) * NPG + v] = h.z;
            Ht[(e + 3) * NPG + v] = h.w;
        }
        // ---- stage W rows into Ws[f*68 + d] (coalesced LDG.128) ----
        #pragma unroll
        for (int i = t; i < D * D / 4; i += NT) {
            float4 w = ((const float4*)W)[i];
            int fw = i >> 4, d4 = (i & 15) * 4;
            *(float4*)&Ws[fw * WS + d4] = w;
        }
        if (t < D) Bs[t] = bias[t];
    }
    __syncthreads();

    // ---- s[e] = sum_v Ht[e,v] ----
    if (t < EPB) {
        const float4* hr = (const float4*)&Ht[t * NPG];
        float a0 = 0.f, a1 = 0.f;
        #pragma unroll
        for (int k = 0; k < NPG / 8; k++) {
            float4 h0 = hr[2 * k], h1 = hr[2 * k + 1];
            a0 += h0.x + h0.y + h0.z + h0.w;
            a1 += h1.x + h1.y + h1.z + h1.w;
        }
        Sv[t] = a0 + a1;
    }

    // ---- phase 1: M[e,f] ;  f = t&63, qq = t>>6, e = j*2+qq ----
    // packed over v-pairs: Ht rows give (v,v+1) pairs from 16B loads.
    {
        const int f = t & 63, qq = t >> 6;
        ull macc2[6] = {0, 0, 0, 0, 0, 0};       // (0,0) fp32 pair

        #pragma unroll
        for (int vc = 0; vc < 2; vc++) {
            float xr[16];
            const float* xg = x + (size_t)b * NPG * D + (vc * 16) * D + f;
            #pragma unroll
            for (int v = 0; v < 16; v++) xr[v] = xg[v * D];   // coalesced

            ull xp[8];
            #pragma unroll
            for (int k = 0; k < 8; k++) xp[k] = pack2(xr[2 * k], xr[2 * k + 1]);

            #pragma unroll
            for (int j = 0; j < 6; j++) {
                int e = j * 2 + qq;
                const ulonglong2* hr = (const ulonglong2*)&Ht[e * NPG + vc * 16];
                #pragma unroll
                for (int k = 0; k < 4; k++) {
                    ulonglong2 h = hr[k];                     // (v0,v1),(v2,v3)
                    ffma2(macc2[j], h.x, xp[2 * k + 0]);
                    ffma2(macc2[j], h.y, xp[2 * k + 1]);
                }
            }
        }
        #pragma unroll
        for (int j = 0; j < 6; j++)
            Ms[(j * 2 + qq) * D + f] = sum2(macc2[j]) * (1.0f / NPG);
    }
    __syncthreads();

    // ---- phase 2: 2D tile, u = t&31, es = t>>5; f0 = u, f1 = u+32 ----
    // packed over d-pairs: both Ms and Ws operands packed from 16B loads.
    {
        const int u = t & 31, es = t >> 5;
        ull acc2a[3] = {0, 0, 0};
        ull acc2b[3] = {0, 0, 0};

        #pragma unroll
        for (int dc = 0; dc < 4; dc++) {
            ulonglong2 wa[4], wb[4];
            const ulonglong2* wra = (const ulonglong2*)&Ws[u * WS + dc * 16];
            const ulonglong2* wrb = (const ulonglong2*)&Ws[(u + 32) * WS + dc * 16];
            #pragma unroll
            for (int k = 0; k < 4; k++) { wa[k] = wra[k]; wb[k] = wrb[k]; }

            #pragma unroll
            for (int j = 0; j < 3; j++) {
                int e = j * 4 + es;
                const ulonglong2* mr = (const ulonglong2*)&Ms[e * D + dc * 16];
                #pragma unroll
                for (int k = 0; k < 4; k++) {
                    ulonglong2 m = mr[k];                     // (d0,d1),(d2,d3)
                    ffma2(acc2a[j], m.x, wa[k].x);
                    ffma2(acc2a[j], m.y, wa[k].y);
                    ffma2(acc2b[j], m.x, wb[k].x);
                    ffma2(acc2b[j], m.y, wb[k].y);
                }
            }
        }

        // relu, h_e store, c fold
        float c0 = 0.f, c1 = 0.f;
        float* he = out + (size_t)B * D + ((size_t)b * E + eq * EPB) * D;
        #pragma unroll
        for (int j = 0; j < 3; j++) {
            int e = j * 4 + es;
            float r0 = fmaxf(sum2(acc2a[j]) + Bs[u], 0.f);
            float r1 = fmaxf(sum2(acc2b[j]) + Bs[u + 32], 0.f);
            he[e * D + u]      = r0;     // coalesced 128B
            he[e * D + u + 32] = r1;     // coalesced 128B
            float sv = Sv[e];
            c0 = fmaf(sv, r0, c0);
            c1 = fmaf(sv, r1, c1);
        }
        Cp[es][u]      = c0;
        Cp[es][u + 32] = c1;
    }
    __syncthreads();

    // ---- partial c -> L2 scratch; last quarter-block per graph reduces ----
    if (t < D) {
        float c = Cp[0][t] + Cp[1][t] + Cp[2][t] + Cp[3][t];
        __stcg(&Cscratch[(eq * B + b) * D + t], c);
    }
    __syncthreads();   // all partial stores happen-before t0's release

    if (t == 0) {
        int old;
        asm volatile("atom.add.acq_rel.gpu.global.s32 %0, [%1], 1;"
                     : "=r"(old) : "l"(&Ctr[b]) : "memory");
        isLast = (old == EQN - 1);
    }
    __syncthreads();   // t0's acquire happens-before consumer loads

    if (isLast) {
        if (t < D) {
            float s = __ldcg(&Cscratch[b * D + t])
                    + __ldcg(&Cscratch[(B + b) * D + t])
                    + __ldcg(&Cscratch[(2 * B + b) * D + t])
                    + __ldcg(&Cscratch[(3 * B + b) * D + t]);
            out[b * D + t] = s * (1.0f / (NPG * E));
        }
        if (t == 0) Ctr[b] = 0;          // clean for next replay
    }
}

extern "C" void kernel_launch(void* const* d_in, const int* in_sizes, int n_in,
                              void* d_out, int out_size) {
    const float* x    = (const float*)d_in[0];   // (V,D)
    const float* Hm   = (const float*)d_in[1];   // (V,E)
    const float* W    = (const float*)d_in[2];   // (D,D)
    const float* bias = (const float*)d_in[3];   // (D,)
    float* out = (float*)d_out;

    dim3 grid(B, EQN);
    hgnn_main_kernel<<<grid, NT>>>(x, Hm, W, bias, out);
}

// round 13
// speedup vs baseline: 1.3281x; 1.1719x over previous
#include <cuda_runtime.h>
#include <cuda_bf16.h>

// HGNN forward, ONE kernel, one block per graph (256 blocks x 256 threads).
//   M[e,d]  = (1/32) * sum_v H[v,e]*x[v,d]
//   ED[e,f] = relu(sum_d M[e,d]*W[f,d] + b[f])  -> h_e
//   c[f]    = (1/(32*48)) sum_e s[e]*ED[e,f]    -> written directly (all e local)
// Output buffer: [ c (B*D) | h_e (B*E*D) ]
//
// R13: whole graph per block. Cuts l1tex (the measured binding pipe) >2x:
//  - W/H staged ONCE per graph (was 4x under e-quartering)
//  - spread W-LDS bytes per graph: 256KB -> 128KB (phase-2 2f-tile, 6e reuse)
//  - no Cscratch / atomics / gpu-scope sync (c reduced in-block)
// FFMA2 (fma.rn.f32x2) retained from R12.

constexpr int V   = 8192;
constexpr int E   = 48;
constexpr int D   = 64;
constexpr int B   = 256;
constexpr int NPG = V / B;     // 32 nodes per graph
constexpr int NT  = 256;
constexpr int WS  = 68;        // W shared row stride (floats): conflict-free LDS.128

typedef unsigned long long ull;

__device__ __forceinline__ void ffma2(ull& acc, ull a, ull b) {
    asm("fma.rn.f32x2 %0, %1, %2, %0;" : "+l"(acc) : "l"(a), "l"(b));
}
__device__ __forceinline__ ull pack2(float lo, float hi) {
    ull r;
    asm("mov.b64 %0, {%1, %2};" : "=l"(r) : "f"(lo), "f"(hi));
    return r;
}
__device__ __forceinline__ float sum2(ull v) {
    float lo, hi;
    asm("mov.b64 {%0, %1}, %2;" : "=f"(lo), "=f"(hi) : "l"(v));
    return lo + hi;
}

__global__ __launch_bounds__(NT, 2) void hgnn_kernel(
    const float* __restrict__ x,     // (V, D)
    const float* __restrict__ Hm,    // (V, E)
    const float* __restrict__ W,     // (D, D) row-major [f][d]
    const float* __restrict__ bias,  // (D,)
    float* __restrict__ out)         // [c | h_e]
{
    __shared__ float Ht[E * NPG];    // 6 KB   Ht[e*32+v]
    __shared__ float Ws[D * WS];     // 17 KB  Ws[f*68+d]
    __shared__ float Ms[E * D];      // 12 KB
    __shared__ float Sv[E];
    __shared__ float Bs[D];
    __shared__ float Cp[8][D];       // 2 KB

    const int b = blockIdx.x;
    const int t = threadIdx.x;

    // ---- stage H transposed + W rows + bias (all coalesced, ONCE/graph) ----
    {
        const float4* hb = (const float4*)(Hm + (size_t)b * NPG * E);
        #pragma unroll
        for (int i = t; i < NPG * E / 4; i += NT) {       // 384; E%4==0
            float4 h = hb[i];
            int base = i * 4;
            int v = base / E;
            int e = base - v * E;
            Ht[(e + 0) * NPG + v] = h.x;
            Ht[(e + 1) * NPG + v] = h.y;
            Ht[(e + 2) * NPG + v] = h.z;
            Ht[(e + 3) * NPG + v] = h.w;
        }
        #pragma unroll
        for (int i = t; i < D * D / 4; i += NT) {         // 1024
            float4 w = ((const float4*)W)[i];
            int fw = i >> 4, d4 = (i & 15) * 4;
            *(float4*)&Ws[fw * WS + d4] = w;
        }
        if (t < D) Bs[t] = bias[t];
    }
    __syncthreads();

    // ---- s[e] = sum_v Ht[e,v] (once per block; small) ----
    if (t < E) {
        const float4* hr = (const float4*)&Ht[t * NPG];
        float a0 = 0.f, a1 = 0.f;
        #pragma unroll
        for (int k = 0; k < NPG / 8; k++) {
            float4 h0 = hr[2 * k], h1 = hr[2 * k + 1];
            a0 += h0.x + h0.y + h0.z + h0.w;
            a1 += h1.x + h1.y + h1.z + h1.w;
        }
        Sv[t] = a0 + a1;
    }

    // ---- phase 1: M[e,f], f = t&63, qq = t>>6, e = j*4+qq, j=0..11 ----
    // FFMA2 over v-pairs; Ht rows give (v,v+1) pairs from 16B bcast loads.
    {
        const int f = t & 63, qq = t >> 6;
        ull macc2[12];
        #pragma unroll
        for (int j = 0; j < 12; j++) macc2[j] = 0;

        #pragma unroll
        for (int vc = 0; vc < 2; vc++) {
            float xr[16];
            const float* xg = x + (size_t)b * NPG * D + (vc * 16) * D + f;
            #pragma unroll
            for (int v = 0; v < 16; v++) xr[v] = xg[v * D];   // coalesced LDG

            ull xp[8];
            #pragma unroll
            for (int k = 0; k < 8; k++) xp[k] = pack2(xr[2 * k], xr[2 * k + 1]);

            #pragma unroll
            for (int j = 0; j < 12; j++) {
                int e = j * 4 + qq;
                const ulonglong2* hr = (const ulonglong2*)&Ht[e * NPG + vc * 16];
                #pragma unroll
                for (int k = 0; k < 4; k++) {
                    ulonglong2 h = hr[k];
                    ffma2(macc2[j], h.x, xp[2 * k + 0]);
                    ffma2(macc2[j], h.y, xp[2 * k + 1]);
                }
            }
        }
        #pragma unroll
        for (int j = 0; j < 12; j++)
            Ms[(j * 4 + qq) * D + f] = sum2(macc2[j]) * (1.0f / NPG);
    }
    __syncthreads();

    // ---- phase 2: tile (6e x 2f); u = t&31, es = t>>5; e = j*8+es ----
    {
        const int u = t & 31, es = t >> 5;
        ull acc2a[6], acc2b[6];
        #pragma unroll
        for (int j = 0; j < 6; j++) { acc2a[j] = 0; acc2b[j] = 0; }

        #pragma unroll
        for (int dc = 0; dc < 4; dc++) {
            ulonglong2 wa[4], wb[4];
            const ulonglong2* wra = (const ulonglong2*)&Ws[u * WS + dc * 16];
            const ulonglong2* wrb = (const ulonglong2*)&Ws[(u + 32) * WS + dc * 16];
            #pragma unroll
            for (int k = 0; k < 4; k++) { wa[k] = wra[k]; wb[k] = wrb[k]; }

            #pragma unroll
            for (int j = 0; j < 6; j++) {
                int e = j * 8 + es;
                const ulonglong2* mr = (const ulonglong2*)&Ms[e * D + dc * 16]; // bcast
                #pragma unroll
                for (int k = 0; k < 4; k++) {
                    ulonglong2 m = mr[k];
                    ffma2(acc2a[j], m.x, wa[k].x);
                    ffma2(acc2a[j], m.y, wa[k].y);
                    ffma2(acc2b[j], m.x, wb[k].x);
                    ffma2(acc2b[j], m.y, wb[k].y);
                }
            }
        }

        // relu, h_e store, c fold
        float c0 = 0.f, c1 = 0.f;
        float* he = out + (size_t)B * D + (size_t)b * E * D;
        const float bf0 = Bs[u], bf1 = Bs[u + 32];
        #pragma unroll
        for (int j = 0; j < 6; j++) {
            int e = j * 8 + es;
            float r0 = fmaxf(sum2(acc2a[j]) + bf0, 0.f);
            float r1 = fmaxf(sum2(acc2b[j]) + bf1, 0.f);
            he[e * D + u]      = r0;     // coalesced
            he[e * D + u + 32] = r1;     // coalesced
            float sv = Sv[e];
            c0 = fmaf(sv, r0, c0);
            c1 = fmaf(sv, r1, c1);
        }
        Cp[es][u]      = c0;
        Cp[es][u + 32] = c1;
    }
    __syncthreads();

    // ---- c: all 48 e are local -> direct write, no scratch/atomics ----
    if (t < D) {
        float s = 0.f;
        #pragma unroll
        for (int k = 0; k < 8; k++) s += Cp[k][t];
        out[b * D + t] = s * (1.0f / (NPG * E));
    }
}

extern "C" void kernel_launch(void* const* d_in, const int* in_sizes, int n_in,
                              void* d_out, int out_size) {
    const float* x    = (const float*)d_in[0];   // (V,D)
    const float* Hm   = (const float*)d_in[1];   // (V,E)
    const float* W    = (const float*)d_in[2];   // (D,D)
    const float* bias = (const float*)d_in[3];   // (D,)
    float* out = (float*)d_out;

    hgnn_kernel<<<B, NT>>>(x, Hm, W, bias, out);
}